// round 4
// baseline (speedup 1.0000x reference)
#include <cuda_runtime.h>
#include <cstdint>

#define NOFF   27
#define SGRID  1024
#define HBITS  21
#define HSIZE  (1u << HBITS)
#define HMASK  (HSIZE - 1u)
#define MAXN   400000
#define BBITS  16
#define NBUCK  (1 << BBITS)
#define BSHIFT 14               // 30-bit key -> top 16 bits
#define AS2W   130              // duplicated-A row stride in floats (s % 8 == 2)

typedef unsigned long long u64;

// ---- static device scratch (no allocations allowed) ----
__device__ uint32_t g_keys[MAXN];      // packed key per original index
__device__ uint32_t g_bkey[MAXN];      // bucket-grouped keys
__device__ uint32_t g_bidx[MAXN];      // bucket-grouped original indices
__device__ uint32_t g_skeys[MAXN];     // fully sorted keys
__device__ uint32_t g_order[MAXN];     // sorted rank -> original index
__device__ int      g_bcount[NBUCK];
__device__ int      g_boffs[NBUCK + 1];
__device__ int      g_bcur[NBUCK];
__device__ int      g_hkey[HSIZE];
__device__ int      g_hval[HSIZE];
__device__ int      g_okeys[NOFF];
__device__ int      g_zidx;

// ---------------- f32x2 helpers ----------------
__device__ __forceinline__ void ffma2(u64& d, u64 a, u64 b) {
    asm("fma.rn.f32x2 %0, %1, %2, %0;" : "+l"(d) : "l"(a), "l"(b));
}
__device__ __forceinline__ u64 dup2(float a) {
    u64 r; asm("mov.b64 %0, {%1, %1};" : "=l"(r) : "f"(a)); return r;
}

// ---------------- clear counters + hash ----------------
__global__ void k_clear() {
    int i = blockIdx.x * blockDim.x + threadIdx.x;
    if (i < (int)HSIZE) g_hkey[i] = -1;
    if (i < NBUCK) g_bcount[i] = 0;
}

// ---------------- pack keys + histogram ----------------
__global__ void k_hist(const int* __restrict__ coords, int n) {
    int i = blockIdx.x * blockDim.x + threadIdx.x;
    if (i < n) {
        int x = coords[3 * i], y = coords[3 * i + 1], z = coords[3 * i + 2];
        uint32_t key = (uint32_t)((x * SGRID + y) * SGRID + z);
        g_keys[i] = key;
        atomicAdd(&g_bcount[key >> BSHIFT], 1);
    }
}

// ---------------- exclusive scan over 65536 buckets (one block) ----------------
__global__ __launch_bounds__(1024) void k_scan(int n) {
    __shared__ int partial[1024];
    int t = threadIdx.x;
    int base = t * (NBUCK / 1024);
    int s = 0;
    #pragma unroll 8
    for (int i = 0; i < NBUCK / 1024; i++) s += g_bcount[base + i];
    partial[t] = s;
    __syncthreads();
    // Hillis-Steele inclusive scan
    for (int off = 1; off < 1024; off <<= 1) {
        int v = (t >= off) ? partial[t - off] : 0;
        __syncthreads();
        partial[t] += v;
        __syncthreads();
    }
    int run = (t == 0) ? 0 : partial[t - 1];
    for (int i = 0; i < NBUCK / 1024; i++) {
        int c = g_bcount[base + i];
        g_boffs[base + i] = run;
        g_bcur[base + i]  = run;
        run += c;
    }
    if (t == 1023) g_boffs[NBUCK] = run;   // == n
}

// ---------------- scatter into bucket groups ----------------
__global__ void k_scatter(int n) {
    int i = blockIdx.x * blockDim.x + threadIdx.x;
    if (i < n) {
        uint32_t key = g_keys[i];
        int pos = atomicAdd(&g_bcur[key >> BSHIFT], 1);
        g_bkey[pos] = key;
        g_bidx[pos] = i;
    }
}

// ---------------- exact rank within bucket + hash insert ----------------
__global__ void k_rank(int n) {
    int p = blockIdx.x * blockDim.x + threadIdx.x;
    if (p < n) {
        uint32_t key = g_bkey[p];
        int b = key >> BSHIFT;
        int s = g_boffs[b], e = g_boffs[b + 1];
        int c = 0;
        for (int j = s; j < e; j++) c += (g_bkey[j] < key);
        int pos = s + c;
        g_skeys[pos] = key;
        g_order[pos] = g_bidx[p];
        // hash insert (key -> sorted rank)
        uint32_t h = (key * 2654435761u) >> (32 - HBITS);
        for (;;) {
            int prev = atomicCAS(&g_hkey[h], -1, (int)key);
            if (prev == -1) { g_hval[h] = pos; break; }
            h = (h + 1) & HMASK;
        }
    }
}

// ---------------- offset keys ----------------
__global__ void k_off(const int* __restrict__ offsets) {
    int k = threadIdx.x;
    if (k < NOFF) {
        int ok = (offsets[3 * k] * SGRID + offsets[3 * k + 1]) * SGRID + offsets[3 * k + 2];
        g_okeys[k] = ok;
        if (ok == 0) g_zidx = k;
    }
}

__device__ __forceinline__ int hlookup(int qk) {
    uint32_t h = ((uint32_t)qk * 2654435761u) >> (32 - HBITS);
    for (;;) {
        int k = g_hkey[h];
        if (k == qk) return g_hval[h];
        if (k == -1) return -1;
        h = (h + 1) & HMASK;
    }
}

// ---------------- fused gather + f32x2 center GEMM + sparse corrections ----
// block: 256 thr; tile 128 rows x 64 cols; micro-tile 4 rows x 8 cols (4 f32x2)
// dynamic smem: As2 (duplicated A) | Ws | js | tk | s_ok
#define SM_AS2  0
#define SM_WS   (128 * AS2W * 4)                       // 66560
#define SM_JS   (SM_WS + 64 * 64 * 4)                  // 82944
#define SM_TK   (SM_JS + NOFF * 128 * 4)               // 96768
#define SM_OK   (SM_TK + 128 * 4)                      // 97280
#define SM_TOT  (SM_OK + 128)                          // 97408

__global__ __launch_bounds__(256) void k_conv(
    const float* __restrict__ feat, const float* __restrict__ W,
    float* __restrict__ out, int n)
{
    extern __shared__ char smbuf[];
    float*    As2  = (float*)(smbuf + SM_AS2);
    float*    Ws   = (float*)(smbuf + SM_WS);
    int*      js   = (int*)(smbuf + SM_JS);
    uint32_t* tk   = (uint32_t*)(smbuf + SM_TK);
    int*      s_ok = (int*)(smbuf + SM_OK);

    const int tid = threadIdx.x;
    const int r0  = blockIdx.x * 128;
    const int zk  = g_zidx;

    if (tid < NOFF) s_ok[tid] = g_okeys[tid];
    if (tid < 128)  tk[tid] = (r0 + tid < n) ? g_skeys[r0 + tid] : 0xFFFFFFFFu;

    // W_center -> smem (layout [cin][cout], contiguous)
    {
        const float4* Wz4 = (const float4*)(W + (size_t)zk * 64 * 64);
        float4* Ws4 = (float4*)Ws;
        for (int i = tid; i < 1024; i += 256) Ws4[i] = Wz4[i];
    }

    // gather A rows through sort permutation, DUPLICATED: As2[r][2k]=As2[r][2k+1]=A[r][k]
    {
        int r = tid >> 1, q = tid & 1;            // 2 threads per row, 32 floats each
        int gr = r0 + r;
        float* dst = As2 + r * AS2W + q * 64;     // duplicated offset
        if (gr < n) {
            const float4* a4 = (const float4*)(feat + (size_t)g_order[gr] * 64) + q * 8;
            #pragma unroll
            for (int v = 0; v < 8; v++) {
                float4 a = a4[v];
                float2* d2 = (float2*)(dst + v * 8);
                d2[0] = make_float2(a.x, a.x);
                d2[1] = make_float2(a.y, a.y);
                d2[2] = make_float2(a.z, a.z);
                d2[3] = make_float2(a.w, a.w);
            }
        } else {
            float2 zz = make_float2(0.f, 0.f);
            float2* d2 = (float2*)dst;
            #pragma unroll
            for (int v = 0; v < 32; v++) d2[v] = zz;
        }
    }
    __syncthreads();

    // hash probes for the 26 non-center offsets (27*128 per block)
    for (int p = tid; p < NOFF * 128; p += 256) {
        int kk = p >> 7, r = p & 127;
        int v = -1;
        if (kk != zk && r0 + r < n) v = hlookup((int)tk[r] + s_ok[kk]);
        js[p] = v;
    }

    // dense center GEMM with packed f32x2 FFMAs
    const int ty = tid >> 3, tx = tid & 7;        // 32 x 8, rows ty*4.., cols tx*8..
    u64 acc[4][4] = {};
    const float* a0p = As2 + (ty * 4 + 0) * AS2W;
    const float* a1p = As2 + (ty * 4 + 1) * AS2W;
    const float* a2p = As2 + (ty * 4 + 2) * AS2W;
    const float* a3p = As2 + (ty * 4 + 3) * AS2W;
    #pragma unroll 8
    for (int k = 0; k < 64; k++) {
        u64 a0 = *(const u64*)(a0p + 2 * k);
        u64 a1 = *(const u64*)(a1p + 2 * k);
        u64 a2 = *(const u64*)(a2p + 2 * k);
        u64 a3 = *(const u64*)(a3p + 2 * k);
        uint4 wA = *(const uint4*)(Ws + k * 64 + tx * 8);
        uint4 wB = *(const uint4*)(Ws + k * 64 + tx * 8 + 4);
        u64 w0 = ((u64)wA.y << 32) | wA.x;
        u64 w1 = ((u64)wA.w << 32) | wA.z;
        u64 w2 = ((u64)wB.y << 32) | wB.x;
        u64 w3 = ((u64)wB.w << 32) | wB.z;
        ffma2(acc[0][0], a0, w0); ffma2(acc[0][1], a0, w1); ffma2(acc[0][2], a0, w2); ffma2(acc[0][3], a0, w3);
        ffma2(acc[1][0], a1, w0); ffma2(acc[1][1], a1, w1); ffma2(acc[1][2], a1, w2); ffma2(acc[1][3], a1, w3);
        ffma2(acc[2][0], a2, w0); ffma2(acc[2][1], a2, w1); ffma2(acc[2][2], a2, w2); ffma2(acc[2][3], a2, w3);
        ffma2(acc[3][0], a3, w0); ffma2(acc[3][1], a3, w1); ffma2(acc[3][2], a3, w2); ffma2(acc[3][3], a3, w3);
    }
    __syncthreads();   // js fully written

    // sparse corrections (rare-taken)
    for (int kk = 0; kk < NOFF; kk++) {
        if (kk == zk) continue;
        const float* Wk = W + (size_t)kk * 64 * 64;
        #pragma unroll
        for (int i = 0; i < 4; i++) {
            int j = js[kk * 128 + ty * 4 + i];
            if (j >= 0) {
                const float* arow = feat + (size_t)g_order[j] * 64;
                for (int k = 0; k < 64; k++) {
                    u64 a = dup2(__ldg(arow + k));
                    uint4 wA = __ldg((const uint4*)(Wk + k * 64 + tx * 8));
                    uint4 wB = __ldg((const uint4*)(Wk + k * 64 + tx * 8 + 4));
                    u64 w0 = ((u64)wA.y << 32) | wA.x;
                    u64 w1 = ((u64)wA.w << 32) | wA.z;
                    u64 w2 = ((u64)wB.y << 32) | wB.x;
                    u64 w3 = ((u64)wB.w << 32) | wB.z;
                    ffma2(acc[i][0], a, w0); ffma2(acc[i][1], a, w1);
                    ffma2(acc[i][2], a, w2); ffma2(acc[i][3], a, w3);
                }
            }
        }
    }

    // write output tile (sorted-order rows)
    #pragma unroll
    for (int i = 0; i < 4; i++) {
        int gr = r0 + ty * 4 + i;
        if (gr < n) {
            u64 row[4] = {acc[i][0], acc[i][1], acc[i][2], acc[i][3]};
            uint4* o = (uint4*)(out + (size_t)gr * 64 + tx * 8);
            o[0] = ((uint4*)row)[0];
            o[1] = ((uint4*)row)[1];
        }
    }
}

// ---------------- launch ----------------
extern "C" void kernel_launch(void* const* d_in, const int* in_sizes, int n_in,
                              void* d_out, int out_size) {
    const float* feat    = (const float*)d_in[0];
    const float* W       = (const float*)d_in[1];
    const int*   coords  = (const int*)d_in[2];
    const int*   offsets = (const int*)d_in[3];
    float*       out     = (float*)d_out;
    const int n = in_sizes[0] / 64;

    static int s_attr_done = 0;
    if (!s_attr_done) {
        cudaFuncSetAttribute(k_conv, cudaFuncAttributeMaxDynamicSharedMemorySize, SM_TOT);
        s_attr_done = 1;
    }

    k_clear<<<(HSIZE + 255) / 256, 256>>>();
    k_hist<<<(n + 255) / 256, 256>>>(coords, n);
    k_scan<<<1, 1024>>>(n);
    k_scatter<<<(n + 255) / 256, 256>>>(n);
    k_rank<<<(n + 255) / 256, 256>>>(n);
    k_off<<<1, 32>>>(offsets);
    k_conv<<<(n + 127) / 128, 256, SM_TOT>>>(feat, W, out, n);
}